// round 3
// baseline (speedup 1.0000x reference)
#include <cuda_runtime.h>
#include <math.h>

// Problem constants
#define Bq 64
#define Tq 512
#define Iq 512
#define Hq 1024
#define Gq 4096      // 4*H
#define Cq 20
#define MTOT (Bq*Tq) // 32768
#define NBLK 128     // persistent blocks (<148 => all co-resident)

// ---- scratch (static device allocations; no cudaMalloc allowed) ----
__device__ float g_xproj[(size_t)MTOT * Gq];   // 512 MB, reused by both layers
__device__ float g_hseq1[(size_t)MTOT * Hq];   // 134 MB (T,B,H)
__device__ float g_hseq2[(size_t)MTOT * Hq];   // 134 MB (T,B,H)
__device__ float g_hbuf[2][Bq * Hq];           // h ping-pong
__device__ float g_emis[(size_t)MTOT * Cq];    // (T,B,C)
__device__ float g_llh[Bq];
__device__ unsigned g_cnt;
__device__ unsigned g_phase;

__device__ __forceinline__ float dot4(float acc, float4 a, float4 b)
{
    acc = fmaf(a.x, b.x, acc);
    acc = fmaf(a.y, b.y, acc);
    acc = fmaf(a.z, b.z, acc);
    acc = fmaf(a.w, b.w, acc);
    return acc;
}

// ============================================================
// Generic 64x64x(BK=16) fp32 SGEMM: Y = X(MxK) * W(NxK)^T + bias
// If remap!=0, X row m = b*T+t and output row becomes t*B+b.
// ============================================================
__global__ void sgemm64(const float* __restrict__ X, const float* __restrict__ W,
                        const float* __restrict__ bias, float* __restrict__ Y,
                        int K, int N, int remap)
{
    __shared__ float Xs[16][72];
    __shared__ float Ws[16][72];
    const int bn = blockIdx.x * 64;
    const int bm = blockIdx.y * 64;
    const int tid = threadIdx.x;
    const int lrow = tid >> 2;
    const int lk   = (tid & 3) << 2;
    const int ty = tid >> 4;
    const int tx = tid & 15;

    float acc[4][4] = {};
    const float* xp = X + (size_t)(bm + lrow) * K + lk;
    const float* wp = W + (size_t)(bn + lrow) * K + lk;

    for (int k0 = 0; k0 < K; k0 += 16) {
        float4 xv = *(const float4*)(xp + k0);
        float4 wv = *(const float4*)(wp + k0);
        Xs[lk+0][lrow]=xv.x; Xs[lk+1][lrow]=xv.y; Xs[lk+2][lrow]=xv.z; Xs[lk+3][lrow]=xv.w;
        Ws[lk+0][lrow]=wv.x; Ws[lk+1][lrow]=wv.y; Ws[lk+2][lrow]=wv.z; Ws[lk+3][lrow]=wv.w;
        __syncthreads();
        #pragma unroll
        for (int k = 0; k < 16; k++) {
            float4 av = *(const float4*)&Xs[k][ty*4];
            float4 bv = *(const float4*)&Ws[k][tx*4];
            float ar[4] = {av.x, av.y, av.z, av.w};
            float br[4] = {bv.x, bv.y, bv.z, bv.w};
            #pragma unroll
            for (int i = 0; i < 4; i++)
                #pragma unroll
                for (int j = 0; j < 4; j++)
                    acc[i][j] = fmaf(ar[i], br[j], acc[i][j]);
        }
        __syncthreads();
    }

    #pragma unroll
    for (int i = 0; i < 4; i++) {
        int m = bm + ty*4 + i;
        int row = remap ? ((m & (Tq-1)) * Bq + (m >> 9)) : m;  // T=512
        #pragma unroll
        for (int j = 0; j < 4; j++) {
            int n = bn + tx*4 + j;
            Y[(size_t)row * N + n] = acc[i][j] + (bias ? bias[n] : 0.0f);
        }
    }
}

// ============================================================
// Software grid barrier (all NBLK blocks resident by construction).
// ============================================================
__device__ __forceinline__ void gridbar(unsigned& myphase)
{
    __syncthreads();
    if (threadIdx.x == 0) {
        __threadfence();
        unsigned old = atomicAdd(&g_cnt, 1u);
        if (old == NBLK - 1) {
            g_cnt = 0;
            __threadfence();
            atomicAdd(&g_phase, 1u);
        } else {
            while (*(volatile unsigned*)&g_phase == myphase) { }
            __threadfence();
        }
    }
    __syncthreads();
    myphase++;
}

// ============================================================
// Persistent LSTM layer: 128 blocks x 256 threads run all T steps.
// Block owns 8 hidden units -> a 64x32 slice of the 64x4096 gate GEMM
// (cols = {g*1024 + j0+0..7 : g in 0..3}), full K=1024 per step.
// Weights L1/L2-resident across steps; c kept in registers; h ping-pong
// in gmem with one grid barrier per step.
// ============================================================
__global__ void __launch_bounds__(256, 1)
lstm_layer(const float* __restrict__ xproj, const float* __restrict__ Whh,
           const float* __restrict__ bhh, float* __restrict__ hseq)
{
    __shared__ float Xs[64][68];   // h tile [row][k] (k-chunk of 64)
    __shared__ float Gs[64][36];   // gate slice [b][s], s = gate*8 + jl

    const int tid = threadIdx.x;
    const int bid = blockIdx.x;
    const int j0  = bid * 8;

    unsigned myphase = *(volatile unsigned*)&g_phase;  // resume-safe across replays

    // GEMM thread coords: tx = col-group (4 cols), ty = row-group (2 rows)
    const int tx = tid & 7;
    const int ty = tid >> 3;
    const int gate = tx >> 1;
    const int ju   = (tx & 1) * 4;
    const float* wbase = Whh + (size_t)(gate * Hq + j0 + ju) * Hq;

    // update-phase: thread handles pairs p = tid, tid+256;  b=p>>3, jl=p&7
    float creg[2] = {0.0f, 0.0f};
    float bh[2][4];
    #pragma unroll
    for (int q = 0; q < 2; q++) {
        int p = tid + q * 256;
        int jl = p & 7;
        #pragma unroll
        for (int g2 = 0; g2 < 4; g2++) bh[q][g2] = bhh[g2 * Hq + j0 + jl];
    }

    // zero h buffer 0 (each block zeroes its 512-float share)
    {
        int idx = bid * 512 + tid;
        g_hbuf[0][idx] = 0.0f;
        g_hbuf[0][idx + 256] = 0.0f;
    }
    gridbar(myphase);

    for (int t = 0; t < Tq; t++) {
        const float* hprev = g_hbuf[t & 1];
        float* hnext = g_hbuf[(t + 1) & 1];

        float acc[2][4] = {};
        for (int kc = 0; kc < Hq; kc += 64) {
            // cooperative load of h k-chunk (bypass L1: cross-kernel-step data)
            #pragma unroll
            for (int i = 0; i < 4; i++) {
                int idx = tid + i * 256;          // 0..1023
                int row = idx >> 4;
                int kq  = idx & 15;
                float4 v = __ldcg((const float4*)(hprev + (size_t)row * Hq + kc + kq * 4));
                *(float4*)&Xs[row][kq * 4] = v;
            }
            __syncthreads();

            const float* wk = wbase + kc;
            #pragma unroll
            for (int k4 = 0; k4 < 64; k4 += 4) {
                float4 xv0 = *(const float4*)&Xs[ty*2    ][k4];
                float4 xv1 = *(const float4*)&Xs[ty*2 + 1][k4];
                float4 wv0 = __ldg((const float4*)(wk + 0 * Hq + k4));
                float4 wv1 = __ldg((const float4*)(wk + 1 * Hq + k4));
                float4 wv2 = __ldg((const float4*)(wk + 2 * Hq + k4));
                float4 wv3 = __ldg((const float4*)(wk + 3 * Hq + k4));
                acc[0][0] = dot4(acc[0][0], xv0, wv0);
                acc[0][1] = dot4(acc[0][1], xv0, wv1);
                acc[0][2] = dot4(acc[0][2], xv0, wv2);
                acc[0][3] = dot4(acc[0][3], xv0, wv3);
                acc[1][0] = dot4(acc[1][0], xv1, wv0);
                acc[1][1] = dot4(acc[1][1], xv1, wv1);
                acc[1][2] = dot4(acc[1][2], xv1, wv2);
                acc[1][3] = dot4(acc[1][3], xv1, wv3);
            }
            __syncthreads();
        }

        // stash gate slice in smem: slice col s = tx*4+c -> (gate = tx>>1, ju)
        #pragma unroll
        for (int r = 0; r < 2; r++)
            *(float4*)&Gs[ty*2 + r][tx*4] = *(float4*)acc[r];
        __syncthreads();

        // pointwise LSTM update
        #pragma unroll
        for (int q = 0; q < 2; q++) {
            int p = tid + q * 256;
            int b = p >> 3, jl = p & 7;
            size_t xb = ((size_t)t * Bq + b) * Gq + j0 + jl;
            float gi = Gs[b][     jl] + xproj[xb         ] + bh[q][0];
            float gf = Gs[b][ 8 + jl] + xproj[xb +     Hq] + bh[q][1];
            float gg = Gs[b][16 + jl] + xproj[xb + 2 * Hq] + bh[q][2];
            float go = Gs[b][24 + jl] + xproj[xb + 3 * Hq] + bh[q][3];
            float ig = 1.0f / (1.0f + expf(-gi));
            float fg = 1.0f / (1.0f + expf(-gf));
            float gv = tanhf(gg);
            float og = 1.0f / (1.0f + expf(-go));
            float cn = fg * creg[q] + ig * gv;
            creg[q] = cn;
            float hn = og * tanhf(cn);
            hnext[(size_t)b * Hq + j0 + jl] = hn;
            hseq[((size_t)t * Bq + b) * Hq + j0 + jl] = hn;
        }
        gridbar(myphase);
    }
}

// ============================================================
// Emissions: e[(t*B+b), c] = h2_row . fc_w[c] + fc_b[c]; one warp/row.
// ============================================================
__global__ void emis_kernel(const float* __restrict__ h2, const float* __restrict__ fcw,
                            const float* __restrict__ fcb, float* __restrict__ e)
{
    int warp = (blockIdx.x * blockDim.x + threadIdx.x) >> 5;
    int lane = threadIdx.x & 31;
    if (warp >= MTOT) return;
    const float* hr = h2 + (size_t)warp * Hq;
    float acc[Cq];
    #pragma unroll
    for (int cc = 0; cc < Cq; cc++) acc[cc] = 0.0f;
    for (int k = lane; k < Hq; k += 32) {
        float hv = hr[k];
        #pragma unroll
        for (int cc = 0; cc < Cq; cc++)
            acc[cc] = fmaf(hv, fcw[cc*Hq + k], acc[cc]);
    }
    #pragma unroll
    for (int cc = 0; cc < Cq; cc++) {
        float v = acc[cc];
        #pragma unroll
        for (int off = 16; off; off >>= 1) v += __shfl_down_sync(0xffffffffu, v, off);
        if (lane == 0) e[(size_t)warp * Cq + cc] = v + fcb[cc];
    }
}

// ============================================================
// CRF NLL per batch element. One warp per b. emissions in (T,B,C).
// ============================================================
__global__ void crf_kernel(const float* __restrict__ e, const int* __restrict__ labels,
                           const float* __restrict__ startt, const float* __restrict__ endt,
                           const float* __restrict__ trans, float* __restrict__ llh)
{
    int b = blockIdx.x;
    int lane = threadIdx.x;
    const int* lb = labels + (size_t)b * Tq;

    // ---- path score ----
    float part = 0.0f;
    int cnt = 0;
    for (int t = 1 + lane; t < Tq; t += 32) {
        int tag  = lb[t];
        int tagp = lb[t-1];
        if (tag != -1)
            part += trans[tagp*Cq + tag] + e[((size_t)t*Bq + b)*Cq + tag];
    }
    for (int t = lane; t < Tq; t += 32) cnt += (lb[t] != -1);
    #pragma unroll
    for (int off = 16; off; off >>= 1) {
        part += __shfl_down_sync(0xffffffffu, part, off);
        cnt  += __shfl_down_sync(0xffffffffu, cnt, off);
    }
    float score = 0.0f;
    if (lane == 0) {
        int tag0 = lb[0];
        score = startt[tag0] + e[(size_t)b*Cq + tag0] + part;
        int last = cnt - 1;
        score += endt[lb[last]];
    }

    // ---- logZ (forward algorithm) ----
    __shared__ float alpha[Cq];
    float tcol[Cq];
    if (lane < Cq) {
        #pragma unroll
        for (int cc = 0; cc < Cq; cc++) tcol[cc] = trans[cc*Cq + lane];
        alpha[lane] = startt[lane] + e[(size_t)b*Cq + lane];
    }
    __syncwarp();
    for (int t = 1; t < Tq; t++) {
        bool m = (lb[t] != -1);
        float av[Cq];
        #pragma unroll
        for (int cc = 0; cc < Cq; cc++) av[cc] = alpha[cc];
        float nxt = 0.0f;
        if (lane < Cq) {
            float mx = -1e30f;
            #pragma unroll
            for (int cc = 0; cc < Cq; cc++) mx = fmaxf(mx, av[cc] + tcol[cc]);
            float s = 0.0f;
            #pragma unroll
            for (int cc = 0; cc < Cq; cc++) s += expf(av[cc] + tcol[cc] - mx);
            nxt = mx + logf(s) + e[((size_t)t*Bq + b)*Cq + lane];
        }
        __syncwarp();
        if (m && lane < Cq) alpha[lane] = nxt;
        __syncwarp();
    }
    float v = (lane < Cq) ? alpha[lane] + endt[lane] : -1e30f;
    float mx = v;
    #pragma unroll
    for (int off = 16; off; off >>= 1) mx = fmaxf(mx, __shfl_xor_sync(0xffffffffu, mx, off));
    float sv = (lane < Cq) ? expf(v - mx) : 0.0f;
    #pragma unroll
    for (int off = 16; off; off >>= 1) sv += __shfl_xor_sync(0xffffffffu, sv, off);
    if (lane == 0) llh[b] = score - (mx + logf(sv));
}

__global__ void finalize_kernel(const float* __restrict__ llh, float* __restrict__ out)
{
    __shared__ float s[64];
    int lane = threadIdx.x;
    s[lane] = llh[lane];
    __syncthreads();
    #pragma unroll
    for (int off = 32; off; off >>= 1) {
        if (lane < off) s[lane] += s[lane + off];
        __syncthreads();
    }
    if (lane == 0) out[0] = -s[0] / (float)Bq;
}

// ============================================================
extern "C" void kernel_launch(void* const* d_in, const int* in_sizes, int n_in,
                              void* d_out, int out_size)
{
    const float* x     = (const float*)d_in[0];
    const int*   labels= (const int*)  d_in[1];
    // d_in[2] = lengths (unused; reference derives mask from labels)
    const float* Wih0  = (const float*)d_in[3];
    const float* Whh0  = (const float*)d_in[4];
    const float* bih0  = (const float*)d_in[5];
    const float* bhh0  = (const float*)d_in[6];
    const float* Wih1  = (const float*)d_in[7];
    const float* Whh1  = (const float*)d_in[8];
    const float* bih1  = (const float*)d_in[9];
    const float* bhh1  = (const float*)d_in[10];
    const float* fcw   = (const float*)d_in[11];
    const float* fcb   = (const float*)d_in[12];
    const float* startt= (const float*)d_in[13];
    const float* endt  = (const float*)d_in[14];
    const float* trans = (const float*)d_in[15];

    float *xproj, *hseq1, *hseq2, *emis, *llh;
    cudaGetSymbolAddress((void**)&xproj, g_xproj);
    cudaGetSymbolAddress((void**)&hseq1, g_hseq1);
    cudaGetSymbolAddress((void**)&hseq2, g_hseq2);
    cudaGetSymbolAddress((void**)&emis,  g_emis);
    cudaGetSymbolAddress((void**)&llh,   g_llh);

    dim3 gsX(Gq/64, MTOT/64);        // (64, 512)

    // ---- layer 1 ----
    sgemm64<<<gsX, 256>>>(x, Wih0, bih0, xproj, Iq, Gq, /*remap=*/1);
    lstm_layer<<<NBLK, 256>>>(xproj, Whh0, bhh0, hseq1);

    // ---- layer 2 ----
    sgemm64<<<gsX, 256>>>(hseq1, Wih1, bih1, xproj, Hq, Gq, /*remap=*/0);
    lstm_layer<<<NBLK, 256>>>(xproj, Whh1, bhh1, hseq2);

    // ---- emissions + CRF ----
    emis_kernel<<<(MTOT*32)/256, 256>>>(hseq2, fcw, fcb, emis);
    crf_kernel<<<Bq, 32>>>(emis, labels, startt, endt, trans, llh);
    finalize_kernel<<<1, 64>>>(llh, (float*)d_out);
}

// round 4
// speedup vs baseline: 1.0007x; 1.0007x over previous
#include <cuda_runtime.h>
#include <math.h>

// Problem constants
#define Bq 64
#define Tq 512
#define Iq 512
#define Hq 1024
#define Gq 4096      // 4*H
#define Cq 20
#define MTOT (Bq*Tq) // 32768
#define NBLK 128     // persistent blocks (<148 => all co-resident)

// ---- scratch (static device allocations; no cudaMalloc allowed) ----
__device__ float g_xproj[(size_t)MTOT * Gq];   // 512 MB, reused by both layers
__device__ float g_hseq1[(size_t)MTOT * Hq];   // 134 MB (T,B,H)
__device__ float g_hseq2[(size_t)MTOT * Hq];   // 134 MB (T,B,H)
__device__ float g_hbuf[2][Bq * Hq];           // h ping-pong
__device__ float g_emis[(size_t)MTOT * Cq];    // (T,B,C)
__device__ float g_llh[Bq];
__device__ unsigned g_cnt;
__device__ unsigned g_phase;

__device__ __forceinline__ float dot4(float acc, float4 a, float4 b)
{
    acc = fmaf(a.x, b.x, acc);
    acc = fmaf(a.y, b.y, acc);
    acc = fmaf(a.z, b.z, acc);
    acc = fmaf(a.w, b.w, acc);
    return acc;
}

// ============================================================
// Generic 64x64x(BK=16) fp32 SGEMM: Y = X(MxK) * W(NxK)^T + bias
// If remap!=0, X row m = b*T+t and output row becomes t*B+b.
// ============================================================
__global__ void sgemm64(const float* __restrict__ X, const float* __restrict__ W,
                        const float* __restrict__ bias, float* __restrict__ Y,
                        int K, int N, int remap)
{
    __shared__ float Xs[16][72];
    __shared__ float Ws[16][72];
    const int bn = blockIdx.x * 64;
    const int bm = blockIdx.y * 64;
    const int tid = threadIdx.x;
    const int lrow = tid >> 2;
    const int lk   = (tid & 3) << 2;
    const int ty = tid >> 4;
    const int tx = tid & 15;

    float acc[4][4] = {};
    const float* xp = X + (size_t)(bm + lrow) * K + lk;
    const float* wp = W + (size_t)(bn + lrow) * K + lk;

    for (int k0 = 0; k0 < K; k0 += 16) {
        float4 xv = *(const float4*)(xp + k0);
        float4 wv = *(const float4*)(wp + k0);
        Xs[lk+0][lrow]=xv.x; Xs[lk+1][lrow]=xv.y; Xs[lk+2][lrow]=xv.z; Xs[lk+3][lrow]=xv.w;
        Ws[lk+0][lrow]=wv.x; Ws[lk+1][lrow]=wv.y; Ws[lk+2][lrow]=wv.z; Ws[lk+3][lrow]=wv.w;
        __syncthreads();
        #pragma unroll
        for (int k = 0; k < 16; k++) {
            float4 av = *(const float4*)&Xs[k][ty*4];
            float4 bv = *(const float4*)&Ws[k][tx*4];
            float ar[4] = {av.x, av.y, av.z, av.w};
            float br[4] = {bv.x, bv.y, bv.z, bv.w};
            #pragma unroll
            for (int i = 0; i < 4; i++)
                #pragma unroll
                for (int j = 0; j < 4; j++)
                    acc[i][j] = fmaf(ar[i], br[j], acc[i][j]);
        }
        __syncthreads();
    }

    #pragma unroll
    for (int i = 0; i < 4; i++) {
        int m = bm + ty*4 + i;
        int row = remap ? ((m & (Tq-1)) * Bq + (m >> 9)) : m;  // T=512
        #pragma unroll
        for (int j = 0; j < 4; j++) {
            int n = bn + tx*4 + j;
            Y[(size_t)row * N + n] = acc[i][j] + (bias ? bias[n] : 0.0f);
        }
    }
}

// ============================================================
// Software grid barrier (all NBLK blocks resident by construction).
// ============================================================
__device__ __forceinline__ void gridbar(unsigned& myphase)
{
    __syncthreads();
    if (threadIdx.x == 0) {
        __threadfence();
        unsigned old = atomicAdd(&g_cnt, 1u);
        if (old == NBLK - 1) {
            g_cnt = 0;
            __threadfence();
            atomicAdd(&g_phase, 1u);
        } else {
            while (*(volatile unsigned*)&g_phase == myphase) { }
            __threadfence();
        }
    }
    __syncthreads();
    myphase++;
}

// ============================================================
// Persistent LSTM layer: 128 blocks x 256 threads run all T steps.
// Block owns 8 hidden units -> a 64x32 slice of the 64x4096 gate GEMM
// (cols = {g*1024 + j0+0..7 : g in 0..3}), full K=1024 per step.
// Weights L1/L2-resident across steps; c kept in registers; h ping-pong
// in gmem with one grid barrier per step.
// ============================================================
__global__ void __launch_bounds__(256, 1)
lstm_layer(const float* __restrict__ xproj, const float* __restrict__ Whh,
           const float* __restrict__ bhh, float* __restrict__ hseq)
{
    __shared__ float Xs[64][68];   // h tile [row][k] (k-chunk of 64)
    __shared__ float Gs[64][36];   // gate slice [b][s], s = gate*8 + jl

    const int tid = threadIdx.x;
    const int bid = blockIdx.x;
    const int j0  = bid * 8;

    unsigned myphase = *(volatile unsigned*)&g_phase;  // resume-safe across replays

    // GEMM thread coords: tx = col-group (4 cols), ty = row-group (2 rows)
    const int tx = tid & 7;
    const int ty = tid >> 3;
    const int gate = tx >> 1;
    const int ju   = (tx & 1) * 4;
    const float* wbase = Whh + (size_t)(gate * Hq + j0 + ju) * Hq;

    // update-phase: thread handles pairs p = tid, tid+256;  b=p>>3, jl=p&7
    float creg[2] = {0.0f, 0.0f};
    float bh[2][4];
    #pragma unroll
    for (int q = 0; q < 2; q++) {
        int p = tid + q * 256;
        int jl = p & 7;
        #pragma unroll
        for (int g2 = 0; g2 < 4; g2++) bh[q][g2] = bhh[g2 * Hq + j0 + jl];
    }

    // zero h buffer 0 (each block zeroes its 512-float share)
    {
        int idx = bid * 512 + tid;
        g_hbuf[0][idx] = 0.0f;
        g_hbuf[0][idx + 256] = 0.0f;
    }
    gridbar(myphase);

    for (int t = 0; t < Tq; t++) {
        const float* hprev = g_hbuf[t & 1];
        float* hnext = g_hbuf[(t + 1) & 1];

        float acc[2][4] = {};
        for (int kc = 0; kc < Hq; kc += 64) {
            // cooperative load of h k-chunk (bypass L1: cross-kernel-step data)
            #pragma unroll
            for (int i = 0; i < 4; i++) {
                int idx = tid + i * 256;          // 0..1023
                int row = idx >> 4;
                int kq  = idx & 15;
                float4 v = __ldcg((const float4*)(hprev + (size_t)row * Hq + kc + kq * 4));
                *(float4*)&Xs[row][kq * 4] = v;
            }
            __syncthreads();

            const float* wk = wbase + kc;
            #pragma unroll
            for (int k4 = 0; k4 < 64; k4 += 4) {
                float4 xv0 = *(const float4*)&Xs[ty*2    ][k4];
                float4 xv1 = *(const float4*)&Xs[ty*2 + 1][k4];
                float4 wv0 = __ldg((const float4*)(wk + 0 * Hq + k4));
                float4 wv1 = __ldg((const float4*)(wk + 1 * Hq + k4));
                float4 wv2 = __ldg((const float4*)(wk + 2 * Hq + k4));
                float4 wv3 = __ldg((const float4*)(wk + 3 * Hq + k4));
                acc[0][0] = dot4(acc[0][0], xv0, wv0);
                acc[0][1] = dot4(acc[0][1], xv0, wv1);
                acc[0][2] = dot4(acc[0][2], xv0, wv2);
                acc[0][3] = dot4(acc[0][3], xv0, wv3);
                acc[1][0] = dot4(acc[1][0], xv1, wv0);
                acc[1][1] = dot4(acc[1][1], xv1, wv1);
                acc[1][2] = dot4(acc[1][2], xv1, wv2);
                acc[1][3] = dot4(acc[1][3], xv1, wv3);
            }
            __syncthreads();
        }

        // stash gate slice in smem: slice col s = tx*4+c -> (gate = tx>>1, ju)
        #pragma unroll
        for (int r = 0; r < 2; r++)
            *(float4*)&Gs[ty*2 + r][tx*4] = *(float4*)acc[r];
        __syncthreads();

        // pointwise LSTM update
        #pragma unroll
        for (int q = 0; q < 2; q++) {
            int p = tid + q * 256;
            int b = p >> 3, jl = p & 7;
            size_t xb = ((size_t)t * Bq + b) * Gq + j0 + jl;
            float gi = Gs[b][     jl] + xproj[xb         ] + bh[q][0];
            float gf = Gs[b][ 8 + jl] + xproj[xb +     Hq] + bh[q][1];
            float gg = Gs[b][16 + jl] + xproj[xb + 2 * Hq] + bh[q][2];
            float go = Gs[b][24 + jl] + xproj[xb + 3 * Hq] + bh[q][3];
            float ig = 1.0f / (1.0f + expf(-gi));
            float fg = 1.0f / (1.0f + expf(-gf));
            float gv = tanhf(gg);
            float og = 1.0f / (1.0f + expf(-go));
            float cn = fg * creg[q] + ig * gv;
            creg[q] = cn;
            float hn = og * tanhf(cn);
            hnext[(size_t)b * Hq + j0 + jl] = hn;
            hseq[((size_t)t * Bq + b) * Hq + j0 + jl] = hn;
        }
        gridbar(myphase);
    }
}

// ============================================================
// Emissions: e[(t*B+b), c] = h2_row . fc_w[c] + fc_b[c]; one warp/row.
// ============================================================
__global__ void emis_kernel(const float* __restrict__ h2, const float* __restrict__ fcw,
                            const float* __restrict__ fcb, float* __restrict__ e)
{
    int warp = (blockIdx.x * blockDim.x + threadIdx.x) >> 5;
    int lane = threadIdx.x & 31;
    if (warp >= MTOT) return;
    const float* hr = h2 + (size_t)warp * Hq;
    float acc[Cq];
    #pragma unroll
    for (int cc = 0; cc < Cq; cc++) acc[cc] = 0.0f;
    for (int k = lane; k < Hq; k += 32) {
        float hv = hr[k];
        #pragma unroll
        for (int cc = 0; cc < Cq; cc++)
            acc[cc] = fmaf(hv, fcw[cc*Hq + k], acc[cc]);
    }
    #pragma unroll
    for (int cc = 0; cc < Cq; cc++) {
        float v = acc[cc];
        #pragma unroll
        for (int off = 16; off; off >>= 1) v += __shfl_down_sync(0xffffffffu, v, off);
        if (lane == 0) e[(size_t)warp * Cq + cc] = v + fcb[cc];
    }
}

// ============================================================
// CRF NLL per batch element. One warp per b. emissions in (T,B,C).
// ============================================================
__global__ void crf_kernel(const float* __restrict__ e, const int* __restrict__ labels,
                           const float* __restrict__ startt, const float* __restrict__ endt,
                           const float* __restrict__ trans, float* __restrict__ llh)
{
    int b = blockIdx.x;
    int lane = threadIdx.x;
    const int* lb = labels + (size_t)b * Tq;

    // ---- path score ----
    float part = 0.0f;
    int cnt = 0;
    for (int t = 1 + lane; t < Tq; t += 32) {
        int tag  = lb[t];
        int tagp = lb[t-1];
        if (tag != -1)
            part += trans[tagp*Cq + tag] + e[((size_t)t*Bq + b)*Cq + tag];
    }
    for (int t = lane; t < Tq; t += 32) cnt += (lb[t] != -1);
    #pragma unroll
    for (int off = 16; off; off >>= 1) {
        part += __shfl_down_sync(0xffffffffu, part, off);
        cnt  += __shfl_down_sync(0xffffffffu, cnt, off);
    }
    float score = 0.0f;
    if (lane == 0) {
        int tag0 = lb[0];
        score = startt[tag0] + e[(size_t)b*Cq + tag0] + part;
        int last = cnt - 1;
        score += endt[lb[last]];
    }

    // ---- logZ (forward algorithm) ----
    __shared__ float alpha[Cq];
    float tcol[Cq];
    if (lane < Cq) {
        #pragma unroll
        for (int cc = 0; cc < Cq; cc++) tcol[cc] = trans[cc*Cq + lane];
        alpha[lane] = startt[lane] + e[(size_t)b*Cq + lane];
    }
    __syncwarp();
    for (int t = 1; t < Tq; t++) {
        bool m = (lb[t] != -1);
        float av[Cq];
        #pragma unroll
        for (int cc = 0; cc < Cq; cc++) av[cc] = alpha[cc];
        float nxt = 0.0f;
        if (lane < Cq) {
            float mx = -1e30f;
            #pragma unroll
            for (int cc = 0; cc < Cq; cc++) mx = fmaxf(mx, av[cc] + tcol[cc]);
            float s = 0.0f;
            #pragma unroll
            for (int cc = 0; cc < Cq; cc++) s += expf(av[cc] + tcol[cc] - mx);
            nxt = mx + logf(s) + e[((size_t)t*Bq + b)*Cq + lane];
        }
        __syncwarp();
        if (m && lane < Cq) alpha[lane] = nxt;
        __syncwarp();
    }
    float v = (lane < Cq) ? alpha[lane] + endt[lane] : -1e30f;
    float mx = v;
    #pragma unroll
    for (int off = 16; off; off >>= 1) mx = fmaxf(mx, __shfl_xor_sync(0xffffffffu, mx, off));
    float sv = (lane < Cq) ? expf(v - mx) : 0.0f;
    #pragma unroll
    for (int off = 16; off; off >>= 1) sv += __shfl_xor_sync(0xffffffffu, sv, off);
    if (lane == 0) llh[b] = score - (mx + logf(sv));
}

__global__ void finalize_kernel(const float* __restrict__ llh, float* __restrict__ out)
{
    __shared__ float s[64];
    int lane = threadIdx.x;
    s[lane] = llh[lane];
    __syncthreads();
    #pragma unroll
    for (int off = 32; off; off >>= 1) {
        if (lane < off) s[lane] += s[lane + off];
        __syncthreads();
    }
    if (lane == 0) out[0] = -s[0] / (float)Bq;
}

// ============================================================
extern "C" void kernel_launch(void* const* d_in, const int* in_sizes, int n_in,
                              void* d_out, int out_size)
{
    const float* x     = (const float*)d_in[0];
    const int*   labels= (const int*)  d_in[1];
    // d_in[2] = lengths (unused; reference derives mask from labels)
    const float* Wih0  = (const float*)d_in[3];
    const float* Whh0  = (const float*)d_in[4];
    const float* bih0  = (const float*)d_in[5];
    const float* bhh0  = (const float*)d_in[6];
    const float* Wih1  = (const float*)d_in[7];
    const float* Whh1  = (const float*)d_in[8];
    const float* bih1  = (const float*)d_in[9];
    const float* bhh1  = (const float*)d_in[10];
    const float* fcw   = (const float*)d_in[11];
    const float* fcb   = (const float*)d_in[12];
    const float* startt= (const float*)d_in[13];
    const float* endt  = (const float*)d_in[14];
    const float* trans = (const float*)d_in[15];

    float *xproj, *hseq1, *hseq2, *emis, *llh;
    cudaGetSymbolAddress((void**)&xproj, g_xproj);
    cudaGetSymbolAddress((void**)&hseq1, g_hseq1);
    cudaGetSymbolAddress((void**)&hseq2, g_hseq2);
    cudaGetSymbolAddress((void**)&emis,  g_emis);
    cudaGetSymbolAddress((void**)&llh,   g_llh);

    dim3 gsX(Gq/64, MTOT/64);        // (64, 512)

    // ---- layer 1 ----
    sgemm64<<<gsX, 256>>>(x, Wih0, bih0, xproj, Iq, Gq, /*remap=*/1);
    lstm_layer<<<NBLK, 256>>>(xproj, Whh0, bhh0, hseq1);

    // ---- layer 2 ----
    sgemm64<<<gsX, 256>>>(hseq1, Wih1, bih1, xproj, Hq, Gq, /*remap=*/0);
    lstm_layer<<<NBLK, 256>>>(xproj, Whh1, bhh1, hseq2);

    // ---- emissions + CRF ----
    emis_kernel<<<(MTOT*32)/256, 256>>>(hseq2, fcw, fcb, emis);
    crf_kernel<<<Bq, 32>>>(emis, labels, startt, endt, trans, llh);
    finalize_kernel<<<1, 64>>>(llh, (float*)d_out);
}

// round 5
// speedup vs baseline: 5.7676x; 5.7634x over previous
#include <cuda_runtime.h>
#include <math.h>
#include <stdint.h>

// Problem constants
#define Bq 64
#define Tq 512
#define Iq 512
#define Hq 1024
#define Gq 4096      // 4*H
#define Cq 20
#define MTOT (Bq*Tq) // 32768
#define NBLK 128     // persistent blocks (<148 => all co-resident)

// lstm_layer shared-memory layout (floats)
#define WPAD 1028                 // 1024 + 4
#define HPAD 132                  // 128 + 4
#define HBUF (64*HPAD)            // one h chunk buffer: 8448 floats
#define WOFF 0                    // weights: 32 x WPAD = 32896
#define HOFF (32*WPAD)            // h double buffer: 2*HBUF = 16896
#define GOFF (HOFF + 2*HBUF)      // gate tile: 64 x 36 = 2304
#define SMEM_FLOATS (GOFF + 64*36)
#define SMEM_BYTES (SMEM_FLOATS * 4)

// ---- scratch (static device allocations; no cudaMalloc allowed) ----
__device__ float g_xproj[(size_t)MTOT * Gq];   // 512 MB, reused by both layers
__device__ float g_hseq1[(size_t)MTOT * Hq];   // 134 MB (T,B,H)
__device__ float g_hseq2[(size_t)MTOT * Hq];   // 134 MB (T,B,H)
__device__ float g_hbuf[2][Bq * Hq];           // h ping-pong
__device__ float g_emis[(size_t)MTOT * Cq];    // (T,B,C)
__device__ float g_llh[Bq];
__device__ unsigned g_cnt;
__device__ unsigned g_phase;

__device__ __forceinline__ float dot4(float acc, float4 a, float4 b)
{
    acc = fmaf(a.x, b.x, acc);
    acc = fmaf(a.y, b.y, acc);
    acc = fmaf(a.z, b.z, acc);
    acc = fmaf(a.w, b.w, acc);
    return acc;
}

__device__ __forceinline__ void cp_async16(void* smem_dst, const void* gmem_src)
{
    uint32_t s = (uint32_t)__cvta_generic_to_shared(smem_dst);
    asm volatile("cp.async.cg.shared.global [%0], [%1], 16;\n" :: "r"(s), "l"(gmem_src));
}
__device__ __forceinline__ void cp_commit()
{
    asm volatile("cp.async.commit_group;\n");
}
__device__ __forceinline__ void cp_wait0()
{
    asm volatile("cp.async.wait_group 0;\n");
}

// ============================================================
// 128x64x(BK=16) fp32 SGEMM: Y = X(MxK) * W(NxK)^T + bias
// grid (N/64, M/128), 256 threads, 8x4 per thread.
// If remap!=0, X row m = b*T+t and output row becomes t*B+b.
// ============================================================
__global__ void __launch_bounds__(256)
sgemm128(const float* __restrict__ X, const float* __restrict__ W,
         const float* __restrict__ bias, float* __restrict__ Y,
         int K, int remap)
{
    __shared__ float Xs[16][132];
    __shared__ float Ws[16][68];
    const int bn = blockIdx.x * 64;
    const int bm = blockIdx.y * 128;
    const int tid = threadIdx.x;
    const int ty = tid >> 4;      // 0..15 -> m0 = ty*8
    const int tx = tid & 15;      // n0 = tx*4

    float acc[8][4] = {};

    for (int k0 = 0; k0 < K; k0 += 16) {
        // load X tile: 128 rows x 16 k (2 float4 per thread)
        #pragma unroll
        for (int l = 0; l < 2; l++) {
            int idx = tid + l * 256;
            int r = idx >> 2;
            int kk = (idx & 3) * 4;
            float4 v = *(const float4*)(X + (size_t)(bm + r) * K + k0 + kk);
            Xs[kk+0][r] = v.x; Xs[kk+1][r] = v.y;
            Xs[kk+2][r] = v.z; Xs[kk+3][r] = v.w;
        }
        // load W tile: 64 rows x 16 k (1 float4 per thread)
        {
            int r = tid >> 2;
            int kk = (tid & 3) * 4;
            float4 v = *(const float4*)(W + (size_t)(bn + r) * K + k0 + kk);
            Ws[kk+0][r] = v.x; Ws[kk+1][r] = v.y;
            Ws[kk+2][r] = v.z; Ws[kk+3][r] = v.w;
        }
        __syncthreads();

        #pragma unroll
        for (int k = 0; k < 16; k++) {
            float4 a0 = *(const float4*)&Xs[k][ty*8];
            float4 a1 = *(const float4*)&Xs[k][ty*8 + 4];
            float4 b0 = *(const float4*)&Ws[k][tx*4];
            float ar[8] = {a0.x, a0.y, a0.z, a0.w, a1.x, a1.y, a1.z, a1.w};
            float br[4] = {b0.x, b0.y, b0.z, b0.w};
            #pragma unroll
            for (int i = 0; i < 8; i++)
                #pragma unroll
                for (int j = 0; j < 4; j++)
                    acc[i][j] = fmaf(ar[i], br[j], acc[i][j]);
        }
        __syncthreads();
    }

    float4 bv = *(const float4*)(bias + bn + tx*4);
    #pragma unroll
    for (int i = 0; i < 8; i++) {
        int m = bm + ty*8 + i;
        int row = remap ? ((m & (Tq-1)) * Bq + (m >> 9)) : m;
        float4 o;
        o.x = acc[i][0] + bv.x; o.y = acc[i][1] + bv.y;
        o.z = acc[i][2] + bv.z; o.w = acc[i][3] + bv.w;
        *(float4*)(Y + (size_t)row * Gq + bn + tx*4) = o;
    }
}

// ============================================================
// Software grid barrier (all NBLK blocks resident by construction).
// ============================================================
__device__ __forceinline__ void gridbar(unsigned& myphase)
{
    __syncthreads();
    if (threadIdx.x == 0) {
        __threadfence();
        unsigned old = atomicAdd(&g_cnt, 1u);
        if (old == NBLK - 1) {
            g_cnt = 0;
            __threadfence();
            atomicAdd(&g_phase, 1u);
        } else {
            while (*(volatile unsigned*)&g_phase == myphase) { }
            __threadfence();
        }
    }
    __syncthreads();
    myphase++;
}

// ============================================================
// Persistent LSTM layer: 128 blocks x 256 threads, all T steps.
// Block owns 32 gate-cols (8 h-units x 4 gates).
// Whh slice (32x1024 = 128KB) lives in SMEM for the whole layer.
// h tile streamed per step in 128-k chunks, double-buffered cp.async.
// GEMM: thread tile 8b x 4n, 4-way k-split; smem reduction.
// c state in registers; h ping-pong in gmem + grid barrier per step.
// ============================================================
__global__ void __launch_bounds__(256, 1)
lstm_layer(const float* __restrict__ xproj, const float* __restrict__ Whh,
           const float* __restrict__ bhh, float* __restrict__ hseq)
{
    extern __shared__ float smem[];
    float* Wsm = smem + WOFF;   // [32][WPAD]
    float* Hsm = smem + HOFF;   // [2][64][HPAD]
    float* Gsm = smem + GOFF;   // [64][36]
    float* Rsm = smem + HOFF;   // reduction scratch (unions with Hsm)

    const int tid = threadIdx.x;
    const int bid = blockIdx.x;
    const int j0  = bid * 8;

    unsigned myphase = *(volatile unsigned*)&g_phase;

    // ---- preload weight slice into smem: rows c=0..31 -> (gate=c>>3, jl=c&7)
    #pragma unroll
    for (int l = 0; l < 32; l++) {
        int idx = tid + l * 256;          // 0..8191 float4 slots
        int c  = idx >> 8;                // 256 float4 per row
        int kq = idx & 255;
        int grow = (c >> 3) * Hq + j0 + (c & 7);
        float4 v = *(const float4*)(Whh + (size_t)grow * Hq + kq * 4);
        *(float4*)(Wsm + c * WPAD + kq * 4) = v;
    }

    // GEMM coords
    const int ks  = tid >> 6;     // 0..3 k-split
    const int pos = tid & 63;
    const int bq  = pos >> 3;     // b = bq + 8i
    const int nq  = pos & 7;      // n = nq + 8j

    // update coords (2 items per thread)
    float creg[2] = {0.0f, 0.0f};
    float bh[2][4];
    #pragma unroll
    for (int q = 0; q < 2; q++) {
        int p = tid + q * 256;
        int jl = p & 7;
        #pragma unroll
        for (int g2 = 0; g2 < 4; g2++) bh[q][g2] = bhh[g2 * Hq + j0 + jl];
    }

    // zero h buffer 0
    {
        int idx = bid * 512 + tid;
        g_hbuf[0][idx] = 0.0f;
        g_hbuf[0][idx + 256] = 0.0f;
    }
    gridbar(myphase);

    for (int t = 0; t < Tq; t++) {
        const float* hprev = g_hbuf[t & 1];
        float* hnext = g_hbuf[(t + 1) & 1];

        // prefetch chunk 0 into buf 0
        #pragma unroll
        for (int l = 0; l < 8; l++) {
            int idx = tid + l * 256;      // 2048 float4
            int row = idx >> 5;
            int kq  = idx & 31;
            cp_async16(Hsm + row * HPAD + kq * 4,
                       hprev + (size_t)row * Hq + kq * 4);
        }
        cp_commit();

        // prefetch this step's xproj gate values (hidden behind GEMM)
        float xg[2][4];
        #pragma unroll
        for (int q = 0; q < 2; q++) {
            int p = tid + q * 256;
            int b = p >> 3, jl = p & 7;
            size_t xb = ((size_t)t * Bq + b) * Gq + j0 + jl;
            #pragma unroll
            for (int g2 = 0; g2 < 4; g2++) xg[q][g2] = xproj[xb + (size_t)g2 * Hq];
        }

        float acc[8][4] = {};
        for (int kc = 0; kc < 8; kc++) {
            const int buf = kc & 1;
            cp_wait0();
            __syncthreads();
            if (kc < 7) {
                float* hdst = Hsm + (buf ^ 1) * HBUF;
                #pragma unroll
                for (int l = 0; l < 8; l++) {
                    int idx = tid + l * 256;
                    int row = idx >> 5;
                    int kq  = idx & 31;
                    cp_async16(hdst + row * HPAD + kq * 4,
                               hprev + (size_t)row * Hq + (kc + 1) * 128 + kq * 4);
                }
                cp_commit();
            }

            const float* hb = Hsm + buf * HBUF + ks * 32;
            const float* wb = Wsm + kc * 128 + ks * 32;
            #pragma unroll
            for (int kk = 0; kk < 32; kk += 4) {
                float4 hv[8];
                #pragma unroll
                for (int i = 0; i < 8; i++)
                    hv[i] = *(const float4*)(hb + (bq + 8*i) * HPAD + kk);
                float4 wv[4];
                #pragma unroll
                for (int j = 0; j < 4; j++)
                    wv[j] = *(const float4*)(wb + (nq + 8*j) * WPAD + kk);
                #pragma unroll
                for (int i = 0; i < 8; i++)
                    #pragma unroll
                    for (int j = 0; j < 4; j++)
                        acc[i][j] = dot4(acc[i][j], hv[i], wv[j]);
            }
        }
        __syncthreads();   // all compute done; Hsm free for reduction

        // k-split reduction through smem
        if (ks > 0) {
            float* rp = Rsm + ((ks - 1) * 64 + pos) * 36;
            #pragma unroll
            for (int i = 0; i < 8; i++)
                *(float4*)(rp + i * 4) = *(float4*)acc[i];
        }
        __syncthreads();
        if (ks == 0) {
            #pragma unroll
            for (int s = 0; s < 3; s++) {
                const float* rp = Rsm + (s * 64 + pos) * 36;
                #pragma unroll
                for (int i = 0; i < 8; i++) {
                    float4 v = *(const float4*)(rp + i * 4);
                    acc[i][0] += v.x; acc[i][1] += v.y;
                    acc[i][2] += v.z; acc[i][3] += v.w;
                }
            }
            #pragma unroll
            for (int i = 0; i < 8; i++) {
                int b = bq + 8*i;
                #pragma unroll
                for (int j = 0; j < 4; j++)
                    Gsm[b * 36 + nq + 8*j] = acc[i][j];
            }
        }
        __syncthreads();

        // pointwise LSTM update
        #pragma unroll
        for (int q = 0; q < 2; q++) {
            int p = tid + q * 256;
            int b = p >> 3, jl = p & 7;
            float gi = Gsm[b*36 +      jl] + xg[q][0] + bh[q][0];
            float gf = Gsm[b*36 +  8 + jl] + xg[q][1] + bh[q][1];
            float gg = Gsm[b*36 + 16 + jl] + xg[q][2] + bh[q][2];
            float go = Gsm[b*36 + 24 + jl] + xg[q][3] + bh[q][3];
            float ig = 1.0f / (1.0f + expf(-gi));
            float fg = 1.0f / (1.0f + expf(-gf));
            float gv = tanhf(gg);
            float og = 1.0f / (1.0f + expf(-go));
            float cn = fg * creg[q] + ig * gv;
            creg[q] = cn;
            float hn = og * tanhf(cn);
            hnext[(size_t)b * Hq + j0 + jl] = hn;
            hseq[((size_t)t * Bq + b) * Hq + j0 + jl] = hn;
        }
        gridbar(myphase);
    }
}

// ============================================================
// Emissions: e[(t*B+b), c] = h2_row . fc_w[c] + fc_b[c]; one warp/row.
// ============================================================
__global__ void emis_kernel(const float* __restrict__ h2, const float* __restrict__ fcw,
                            const float* __restrict__ fcb, float* __restrict__ e)
{
    int warp = (blockIdx.x * blockDim.x + threadIdx.x) >> 5;
    int lane = threadIdx.x & 31;
    if (warp >= MTOT) return;
    const float* hr = h2 + (size_t)warp * Hq;
    float acc[Cq];
    #pragma unroll
    for (int cc = 0; cc < Cq; cc++) acc[cc] = 0.0f;
    for (int k = lane; k < Hq; k += 32) {
        float hv = hr[k];
        #pragma unroll
        for (int cc = 0; cc < Cq; cc++)
            acc[cc] = fmaf(hv, fcw[cc*Hq + k], acc[cc]);
    }
    #pragma unroll
    for (int cc = 0; cc < Cq; cc++) {
        float v = acc[cc];
        #pragma unroll
        for (int off = 16; off; off >>= 1) v += __shfl_down_sync(0xffffffffu, v, off);
        if (lane == 0) e[(size_t)warp * Cq + cc] = v + fcb[cc];
    }
}

// ============================================================
// CRF NLL per batch element. One warp per b. emissions in (T,B,C).
// ============================================================
__global__ void crf_kernel(const float* __restrict__ e, const int* __restrict__ labels,
                           const float* __restrict__ startt, const float* __restrict__ endt,
                           const float* __restrict__ trans, float* __restrict__ llh)
{
    int b = blockIdx.x;
    int lane = threadIdx.x;
    const int* lb = labels + (size_t)b * Tq;

    // ---- path score ----
    float part = 0.0f;
    int cnt = 0;
    for (int t = 1 + lane; t < Tq; t += 32) {
        int tag  = lb[t];
        int tagp = lb[t-1];
        if (tag != -1)
            part += trans[tagp*Cq + tag] + e[((size_t)t*Bq + b)*Cq + tag];
    }
    for (int t = lane; t < Tq; t += 32) cnt += (lb[t] != -1);
    #pragma unroll
    for (int off = 16; off; off >>= 1) {
        part += __shfl_down_sync(0xffffffffu, part, off);
        cnt  += __shfl_down_sync(0xffffffffu, cnt, off);
    }
    float score = 0.0f;
    if (lane == 0) {
        int tag0 = lb[0];
        score = startt[tag0] + e[(size_t)b*Cq + tag0] + part;
        int last = cnt - 1;
        score += endt[lb[last]];
    }

    // ---- logZ (forward algorithm) ----
    __shared__ float alpha[Cq];
    float tcol[Cq];
    if (lane < Cq) {
        #pragma unroll
        for (int cc = 0; cc < Cq; cc++) tcol[cc] = trans[cc*Cq + lane];
        alpha[lane] = startt[lane] + e[(size_t)b*Cq + lane];
    }
    __syncwarp();
    for (int t = 1; t < Tq; t++) {
        bool m = (lb[t] != -1);
        float av[Cq];
        #pragma unroll
        for (int cc = 0; cc < Cq; cc++) av[cc] = alpha[cc];
        float nxt = 0.0f;
        if (lane < Cq) {
            float mx = -1e30f;
            #pragma unroll
            for (int cc = 0; cc < Cq; cc++) mx = fmaxf(mx, av[cc] + tcol[cc]);
            float s = 0.0f;
            #pragma unroll
            for (int cc = 0; cc < Cq; cc++) s += expf(av[cc] + tcol[cc] - mx);
            nxt = mx + logf(s) + e[((size_t)t*Bq + b)*Cq + lane];
        }
        __syncwarp();
        if (m && lane < Cq) alpha[lane] = nxt;
        __syncwarp();
    }
    float v = (lane < Cq) ? alpha[lane] + endt[lane] : -1e30f;
    float mx = v;
    #pragma unroll
    for (int off = 16; off; off >>= 1) mx = fmaxf(mx, __shfl_xor_sync(0xffffffffu, mx, off));
    float sv = (lane < Cq) ? expf(v - mx) : 0.0f;
    #pragma unroll
    for (int off = 16; off; off >>= 1) sv += __shfl_xor_sync(0xffffffffu, sv, off);
    if (lane == 0) llh[b] = score - (mx + logf(sv));
}

__global__ void finalize_kernel(const float* __restrict__ llh, float* __restrict__ out)
{
    __shared__ float s[64];
    int lane = threadIdx.x;
    s[lane] = llh[lane];
    __syncthreads();
    #pragma unroll
    for (int off = 32; off; off >>= 1) {
        if (lane < off) s[lane] += s[lane + off];
        __syncthreads();
    }
    if (lane == 0) out[0] = -s[0] / (float)Bq;
}

// ============================================================
extern "C" void kernel_launch(void* const* d_in, const int* in_sizes, int n_in,
                              void* d_out, int out_size)
{
    const float* x     = (const float*)d_in[0];
    const int*   labels= (const int*)  d_in[1];
    // d_in[2] = lengths (unused; reference derives mask from labels)
    const float* Wih0  = (const float*)d_in[3];
    const float* Whh0  = (const float*)d_in[4];
    const float* bih0  = (const float*)d_in[5];
    const float* bhh0  = (const float*)d_in[6];
    const float* Wih1  = (const float*)d_in[7];
    const float* Whh1  = (const float*)d_in[8];
    const float* bih1  = (const float*)d_in[9];
    const float* bhh1  = (const float*)d_in[10];
    const float* fcw   = (const float*)d_in[11];
    const float* fcb   = (const float*)d_in[12];
    const float* startt= (const float*)d_in[13];
    const float* endt  = (const float*)d_in[14];
    const float* trans = (const float*)d_in[15];

    float *xproj, *hseq1, *hseq2, *emis, *llh;
    cudaGetSymbolAddress((void**)&xproj, g_xproj);
    cudaGetSymbolAddress((void**)&hseq1, g_hseq1);
    cudaGetSymbolAddress((void**)&hseq2, g_hseq2);
    cudaGetSymbolAddress((void**)&emis,  g_emis);
    cudaGetSymbolAddress((void**)&llh,   g_llh);

    cudaFuncSetAttribute(lstm_layer, cudaFuncAttributeMaxDynamicSharedMemorySize, SMEM_BYTES);

    dim3 gsX(Gq/64, MTOT/128);       // (64, 256)

    // ---- layer 1 ----
    sgemm128<<<gsX, 256>>>(x, Wih0, bih0, xproj, Iq, /*remap=*/1);
    lstm_layer<<<NBLK, 256, SMEM_BYTES>>>(xproj, Whh0, bhh0, hseq1);

    // ---- layer 2 ----
    sgemm128<<<gsX, 256>>>(hseq1, Wih1, bih1, xproj, Hq, /*remap=*/0);
    lstm_layer<<<NBLK, 256, SMEM_BYTES>>>(xproj, Whh1, bhh1, hseq2);

    // ---- emissions + CRF ----
    emis_kernel<<<(MTOT*32)/256, 256>>>(hseq2, fcw, fcb, emis);
    crf_kernel<<<Bq, 32>>>(emis, labels, startt, endt, trans, llh);
    finalize_kernel<<<1, 64>>>(llh, (float*)d_out);
}